// round 15
// baseline (speedup 1.0000x reference)
#include <cuda_runtime.h>
#include <cuda_bf16.h>
#include <math.h>
#include <stdint.h>

#define BB 4
#define TT 2048
#define CC 1024
#define HH 16
#define DH 64

// Scratch (device globals: allocation-free)
__device__ __nv_bfloat16 g_qb[BB*HH*TT*DH];        // [b,h,t,d] bf16, scaled log2e/32
__device__ __nv_bfloat16 g_kb[BB*HH*TT*DH];        // [b,h,t,d] bf16, kperm layout
__device__ __nv_bfloat16 g_vb[BB*HH*TT*DH];        // [b,h,d,t] bf16 (V^T), kperm layout
__device__ float g_vs[BB*HH*DH];                   // per-(b,h,d) sum of V over t
__device__ float g_o[BB*TT*CC];                    // [b,t,c] tf32-rounded, wperm layout
__device__ float g_wp[CC*CC];                      // Wp tf32-rounded, wperm layout

// ---------------------------------------------------------------------------
// helpers
// ---------------------------------------------------------------------------
__device__ __forceinline__ uint32_t f2tf(float f) {
    uint32_t u;
    asm("cvt.rna.tf32.f32 %0, %1;" : "=r"(u) : "f"(f));
    return u;
}

__device__ __forceinline__ float ex2f(float x) {
    float r;
    asm("ex2.approx.f32 %0, %1;" : "=f"(r) : "f"(x));
    return r;
}

__device__ __forceinline__ uint32_t pk_bf16(float lo, float hi) {
    __nv_bfloat162 t = __float22bfloat162_rn(make_float2(lo, hi));
    return *(uint32_t*)&t;
}

__device__ __forceinline__ void mma_tf32(float4& d,
                                         uint32_t a0, uint32_t a1, uint32_t a2, uint32_t a3,
                                         uint32_t b0, uint32_t b1) {
    asm volatile(
        "mma.sync.aligned.m16n8k8.row.col.f32.tf32.tf32.f32 "
        "{%0,%1,%2,%3}, {%4,%5,%6,%7}, {%8,%9}, {%0,%1,%2,%3};\n"
        : "+f"(d.x), "+f"(d.y), "+f"(d.z), "+f"(d.w)
        : "r"(a0), "r"(a1), "r"(a2), "r"(a3), "r"(b0), "r"(b1));
}

__device__ __forceinline__ void mma_bf16(float4& d,
                                         uint32_t a0, uint32_t a1, uint32_t a2, uint32_t a3,
                                         uint32_t b0, uint32_t b1) {
    asm volatile(
        "mma.sync.aligned.m16n8k16.row.col.f32.bf16.bf16.f32 "
        "{%0,%1,%2,%3}, {%4,%5,%6,%7}, {%8,%9}, {%0,%1,%2,%3};\n"
        : "+f"(d.x), "+f"(d.y), "+f"(d.z), "+f"(d.w)
        : "r"(a0), "r"(a1), "r"(a2), "r"(a3), "r"(b0), "r"(b1));
}

#define PITCH 72   // qkv interleaved tf32 smem pitch

// qkv smem interleave (8-word groups, uint2 frag loads)
__device__ __forceinline__ void perm_st4(uint32_t* rowp, int c4, float4 v) {
    int g = (c4 & ~7) + ((c4 & 4) >> 2);
    rowp[g + 0] = f2tf(v.x);
    rowp[g + 2] = f2tf(v.y);
    rowp[g + 4] = f2tf(v.z);
    rowp[g + 6] = f2tf(v.w);
}

// proj gmem layout: 8-word-group pair interleave (uint2 frag loads)
__device__ __forceinline__ int wperm(int w) {
    return (w & ~7) | ((w & 3) << 1) | ((w >> 2) & 1);
}

// attn K/V gmem layout: within each 16-word (two k-step) chunk of a 32-word
// row, logical word w = kk*8 + c (kk=k-step 0..3, c=0..7; mma b0 at c=q4,
// b1 at c=q4+4) -> slot (kk>>1)*16 + (c&3)*4 + (kk&1)*2 + (c>>2).
// uint4 at q4*4 within a chunk = [b0(kk even), b1(kk even), b0(kk odd), b1(kk odd)].
__device__ __forceinline__ int kperm(int w) {
    int kk = w >> 3, c = w & 7;
    return ((kk >> 1) << 4) | ((c & 3) << 2) | ((kk & 1) << 1) | (c >> 2);
}
// same permutation on bf16 element index within 64-element (32-word) tiles
__device__ __forceinline__ int tperm2(int t) {
    int w = (t >> 1) & 31;
    return (t & ~63) | (kperm(w) << 1) | (t & 1);
}

__device__ __forceinline__ uint32_t smem_u32(const void* p) {
    uint32_t a;
    asm("{ .reg .u64 t; cvta.to.shared.u64 t, %1; cvt.u32.u64 %0, t; }"
        : "=r"(a) : "l"(p));
    return a;
}

__device__ __forceinline__ void cp_async16(uint32_t dst, const void* src) {
    asm volatile("cp.async.cg.shared.global [%0], [%1], 16;\n"
                 :: "r"(dst), "l"(src) : "memory");
}
__device__ __forceinline__ void cp_commit() {
    asm volatile("cp.async.commit_group;\n" ::: "memory");
}
__device__ __forceinline__ void cp_wait0() {
    asm volatile("cp.async.wait_group 0;\n" ::: "memory");
}

// ---------------------------------------------------------------------------
// Kernel 0: Wp -> g_wp (tf32 rna-rounded, wperm layout).
// ---------------------------------------------------------------------------
__global__ void __launch_bounds__(256, 4) wp_perm_kernel(const float* __restrict__ Wp)
{
    int idx = blockIdx.x * 256 + threadIdx.x;
    int row = idx >> 8;
    int c4  = (idx & 255) << 2;
    float4 v = *(const float4*)(Wp + (size_t)row * CC + c4);
    float* dst = g_wp + (size_t)row * CC + (c4 & ~7) + ((c4 & 4) >> 2);
    dst[0] = __uint_as_float(f2tf(v.x));
    dst[2] = __uint_as_float(f2tf(v.y));
    dst[4] = __uint_as_float(f2tf(v.z));
    dst[6] = __uint_as_float(f2tf(v.w));
}

// ---------------------------------------------------------------------------
// Kernel 1: per-head QKV projection, tf32 mma.sync (rna).
// Q bf16 scaled log2e/32 natural; K bf16 kperm; V^T bf16 kperm.
// ---------------------------------------------------------------------------
__global__ void __launch_bounds__(256, 2)
qkv_kernel(const float* __restrict__ x,
           const float* __restrict__ Wq, const float* __restrict__ bq,
           const float* __restrict__ Wk, const float* __restrict__ bk,
           const float* __restrict__ Wv, const float* __restrict__ bv)
{
    extern __shared__ uint32_t smu[];
    uint32_t* xs = smu;
    uint32_t* ws = smu + 128 * PITCH;

    const int tid  = threadIdx.x;
    const int lane = tid & 31;
    const int wid  = tid >> 5;
    const int q4   = lane & 3;
    const int r8   = lane >> 2;
    const int wm   = wid >> 1;
    const int wn   = wid & 1;

    const int t0 = blockIdx.x * 128;
    const int h  = blockIdx.y;
    const int b  = blockIdx.z;
    const size_t bh = (size_t)(b * HH + h);

    const int lrow = tid >> 4;
    const int lc4  = (tid & 15) << 2;

    const float* xb = x + (size_t)(b * TT + t0) * CC + h * DH;
#pragma unroll
    for (int i = 0; i < 8; i++) {
        int r = lrow + i * 16;
        float4 v = *(const float4*)(xb + (size_t)r * CC + lc4);
        perm_st4(xs + r * PITCH, lc4, v);
    }
    {
        const float* Ws[3] = {Wq, Wk, Wv};
#pragma unroll
        for (int m = 0; m < 3; m++) {
            uint32_t* wsm = ws + m * 64 * PITCH;
#pragma unroll
            for (int i = 0; i < 4; i++) {
                int r = lrow + i * 16;
                float4 v = *(const float4*)(Ws[m] + r * 64 + lc4);
                perm_st4(wsm + r * PITCH, lc4, v);
            }
        }
    }
    __syncthreads();

    const float* bias[3] = {bq, bk, bv};
#pragma unroll
    for (int m = 0; m < 3; m++) {
        const uint32_t* wsm = ws + m * 64 * PITCH;
        float4 c[2][4];
#pragma unroll
        for (int i = 0; i < 2; i++)
#pragma unroll
            for (int j = 0; j < 4; j++) c[i][j] = make_float4(0.f, 0.f, 0.f, 0.f);

#pragma unroll
        for (int kk8 = 0; kk8 < 8; kk8++) {
            int off = kk8 * 8 + 2 * q4;
            uint2 a00 = *(const uint2*)(xs + (wm * 32 + r8)          * PITCH + off);
            uint2 a01 = *(const uint2*)(xs + (wm * 32 + r8 + 8)      * PITCH + off);
            uint2 a10 = *(const uint2*)(xs + (wm * 32 + 16 + r8)     * PITCH + off);
            uint2 a11 = *(const uint2*)(xs + (wm * 32 + 16 + r8 + 8) * PITCH + off);
#pragma unroll
            for (int ntl = 0; ntl < 4; ntl++) {
                uint2 bb = *(const uint2*)(wsm + (wn * 32 + ntl * 8 + r8) * PITCH + off);
                mma_tf32(c[0][ntl], a00.x, a01.x, a00.y, a01.y, bb.x, bb.y);
                mma_tf32(c[1][ntl], a10.x, a11.x, a10.y, a11.y, bb.x, bb.y);
            }
        }

        if (m == 0) {
            uint32_t* qw = (uint32_t*)g_qb + (bh * TT + t0) * (DH / 2);
            const float s = 0.03125f * 1.44269504088896f;
#pragma unroll
            for (int mt = 0; mt < 2; mt++) {
                int row = wm * 32 + mt * 16 + r8;
#pragma unroll
                for (int ntl = 0; ntl < 4; ntl++) {
                    int e = wn * 32 + ntl * 8 + 2 * q4;
                    float2 bb = *(const float2*)(bias[0] + e);
                    qw[(size_t)row * 32 + (e >> 1)] =
                        pk_bf16((c[mt][ntl].x + bb.x) * s, (c[mt][ntl].y + bb.y) * s);
                    qw[(size_t)(row + 8) * 32 + (e >> 1)] =
                        pk_bf16((c[mt][ntl].z + bb.x) * s, (c[mt][ntl].w + bb.y) * s);
                }
            }
        } else if (m == 1) {
            uint32_t* kbw = (uint32_t*)g_kb + (bh * TT + t0) * (DH / 2);
#pragma unroll
            for (int mt = 0; mt < 2; mt++) {
                int row = wm * 32 + mt * 16 + r8;
#pragma unroll
                for (int ntl = 0; ntl < 4; ntl++) {
                    int e = wn * 32 + ntl * 8 + 2 * q4;
                    float2 bb = *(const float2*)(bias[1] + e);
                    int wp = kperm(e >> 1);
                    kbw[(size_t)row * 32 + wp] =
                        pk_bf16(c[mt][ntl].x + bb.x, c[mt][ntl].y + bb.y);
                    kbw[(size_t)(row + 8) * 32 + wp] =
                        pk_bf16(c[mt][ntl].z + bb.x, c[mt][ntl].w + bb.y);
                }
            }
        } else {
            __nv_bfloat16* vbb = g_vb + bh * DH * TT;
#pragma unroll
            for (int mt = 0; mt < 2; mt++) {
                int t = t0 + wm * 32 + mt * 16 + r8;
                int tp0 = tperm2(t), tp8 = tperm2(t + 8);
#pragma unroll
                for (int ntl = 0; ntl < 4; ntl++) {
                    int e = wn * 32 + ntl * 8 + 2 * q4;
                    float2 bb = *(const float2*)(bias[2] + e);
                    vbb[(size_t)e       * TT + tp0] = __float2bfloat16_rn(c[mt][ntl].x + bb.x);
                    vbb[(size_t)(e + 1) * TT + tp0] = __float2bfloat16_rn(c[mt][ntl].y + bb.y);
                    vbb[(size_t)e       * TT + tp8] = __float2bfloat16_rn(c[mt][ntl].z + bb.x);
                    vbb[(size_t)(e + 1) * TT + tp8] = __float2bfloat16_rn(c[mt][ntl].w + bb.y);
                }
            }
        }
    }
}

// ---------------------------------------------------------------------------
// Kernel 1b: Vsum[b,h,d] = sum_t V[b,h,d,t] (bf16 rows, permutation-invariant)
// ---------------------------------------------------------------------------
__global__ void __launch_bounds__(256, 4) vsum_kernel()
{
    const int bh   = blockIdx.x;
    const int lane = threadIdx.x & 31;
    const int w    = threadIdx.x >> 5;
    const __nv_bfloat16* vb = g_vb + (size_t)bh * DH * TT;

#pragma unroll
    for (int pass = 0; pass < 8; pass++) {
        int d = pass * 8 + w;
        const uint4* row = (const uint4*)(vb + (size_t)d * TT);
        float s = 0.f;
#pragma unroll
        for (int i = 0; i < 8; i++) {
            uint4 u = row[lane + i * 32];
            float2 f0 = __bfloat1622float2(*(__nv_bfloat162*)&u.x);
            float2 f1 = __bfloat1622float2(*(__nv_bfloat162*)&u.y);
            float2 f2 = __bfloat1622float2(*(__nv_bfloat162*)&u.z);
            float2 f3 = __bfloat1622float2(*(__nv_bfloat162*)&u.w);
            s += (f0.x + f0.y) + (f1.x + f1.y) + (f2.x + f2.y) + (f3.x + f3.y);
        }
        s += __shfl_xor_sync(0xffffffffu, s, 16);
        s += __shfl_xor_sync(0xffffffffu, s, 8);
        s += __shfl_xor_sync(0xffffffffu, s, 4);
        s += __shfl_xor_sync(0xffffffffu, s, 2);
        s += __shfl_xor_sync(0xffffffffu, s, 1);
        if (lane == 0) g_vs[bh * DH + d] = s;
    }
}

// ---------------------------------------------------------------------------
// Kernel 2: flash attention, bf16 m16n8k16, BM=128, 256 threads, 2 CTAs/SM.
// kperm K/V layout -> all B-fragment loads are LDS.128 (32 vs 64 loads per
// warp-iter), pitch 48 (conflict-free for LDS.128 phases). Pure ex2 softmax.
// ---------------------------------------------------------------------------
#define BP 48
#define KVW (64 * BP)

__global__ void __launch_bounds__(256, 2) attn_kernel()
{
    extern __shared__ __align__(1024) uint32_t smu[];

    const int tid  = threadIdx.x;
    const int lane = tid & 31;
    const int wid  = tid >> 5;        // 0..7
    const int q4   = lane & 3;
    const int r8   = lane >> 2;
    const int wrow = wid * 16;

    const int t0 = blockIdx.x * 128;
    const int h  = blockIdx.y;
    const int b  = blockIdx.z;
    const size_t bh = (size_t)(b * HH + h);

    const __nv_bfloat16* kbb = g_kb + bh * TT * DH;
    const __nv_bfloat16* vbb = g_vb + bh * DH * TT;

    const uint32_t smb = smem_u32(smu);

    const int frow[2] = { (tid + 0) >> 3, (tid + 256) >> 3 };
    const int fch     = tid & 7;

    // Q fragments (bf16 pre-scaled, natural words)
    uint32_t qf[4][4];
    {
        const uint32_t* q0 = (const uint32_t*)g_qb +
                             (bh * TT + t0 + wrow + r8) * (DH / 2);
        const uint32_t* q1 = q0 + 8 * (DH / 2);
#pragma unroll
        for (int kk = 0; kk < 4; kk++) {
            qf[kk][0] = q0[kk * 8 + q4];
            qf[kk][1] = q1[kk * 8 + q4];
            qf[kk][2] = q0[kk * 8 + q4 + 4];
            qf[kk][3] = q1[kk * 8 + q4 + 4];
        }
    }

    float4 o[8];
#pragma unroll
    for (int j = 0; j < 8; j++) o[j] = make_float4(0.f, 0.f, 0.f, 0.f);
    float lsum[2] = {0.f, 0.f};

#pragma unroll
    for (int i = 0; i < 2; i++) {
        int r = frow[i];
        cp_async16(smb + (0 * KVW + r * BP + fch * 4) * 4,
                   kbb + (size_t)r * DH + fch * 8);
        cp_async16(smb + (1 * KVW + r * BP + fch * 4) * 4,
                   vbb + (size_t)r * TT + 0 + fch * 8);
    }
    cp_commit();

    for (int it = 0; it < TT / 64; it++) {
        cp_wait0();
        __syncthreads();

        const int buf = it & 1;
        const uint32_t* ks = smu + (2 * buf + 0) * KVW;
        const uint32_t* vs = smu + (2 * buf + 1) * KVW;

        if (it + 1 < TT / 64) {
            int nt = (it + 1) * 64;
            int ob = buf ^ 1;
#pragma unroll
            for (int i = 0; i < 2; i++) {
                int r = frow[i];
                cp_async16(smb + ((2 * ob + 0) * KVW + r * BP + fch * 4) * 4,
                           kbb + (size_t)(nt + r) * DH + fch * 8);
                cp_async16(smb + ((2 * ob + 1) * KVW + r * BP + fch * 4) * 4,
                           vbb + (size_t)r * TT + nt + fch * 8);
            }
            cp_commit();
        }

        // ---- S' = Q' @ K^T ; one LDS.128 covers two k-steps ----
        float4 c[8];
#pragma unroll
        for (int j = 0; j < 8; j++) c[j] = make_float4(0.f, 0.f, 0.f, 0.f);

#pragma unroll
        for (int kp = 0; kp < 2; kp++) {
#pragma unroll
            for (int ntl = 0; ntl < 8; ntl++) {
                uint4 bb = *(const uint4*)(ks + (ntl * 8 + r8) * BP + kp * 16 + q4 * 4);
                mma_bf16(c[ntl], qf[2*kp][0], qf[2*kp][1], qf[2*kp][2], qf[2*kp][3],
                         bb.x, bb.y);
                mma_bf16(c[ntl], qf[2*kp+1][0], qf[2*kp+1][1], qf[2*kp+1][2], qf[2*kp+1][3],
                         bb.z, bb.w);
            }
        }

        // ---- per kk-pair: p = ex2(S'), d = p-1 in registers, then PV ----
#pragma unroll
        for (int kp = 0; kp < 2; kp++) {
            uint32_t A0[4], A1[4];
#pragma unroll
            for (int kq = 0; kq < 2; kq++) {     // kk = 2*kp + kq
                float4 cA = c[4 * kp + 2 * kq];
                float4 cB = c[4 * kp + 2 * kq + 1];
                float pax = ex2f(cA.x), pay = ex2f(cA.y);
                float paz = ex2f(cA.z), paw = ex2f(cA.w);
                float pbx = ex2f(cB.x), pby = ex2f(cB.y);
                float pbz = ex2f(cB.z), pbw = ex2f(cB.w);
                lsum[0] += (pax + pay) + (pbx + pby);
                lsum[1] += (paz + paw) + (pbz + pbw);
                uint32_t* A = kq ? A1 : A0;
                A[0] = pk_bf16(pax - 1.f, pay - 1.f);
                A[1] = pk_bf16(paz - 1.f, paw - 1.f);
                A[2] = pk_bf16(pbx - 1.f, pby - 1.f);
                A[3] = pk_bf16(pbz - 1.f, pbw - 1.f);
            }
#pragma unroll
            for (int dt = 0; dt < 8; dt++) {
                uint4 bb = *(const uint4*)(vs + (dt * 8 + r8) * BP + kp * 16 + q4 * 4);
                mma_bf16(o[dt], A0[0], A0[1], A0[2], A0[3], bb.x, bb.y);
                mma_bf16(o[dt], A1[0], A1[1], A1[2], A1[3], bb.z, bb.w);
            }
        }
    }

    // final l reduction across the quad
#pragma unroll
    for (int j = 0; j < 2; j++) {
        lsum[j] += __shfl_xor_sync(0xffffffffu, lsum[j], 1);
        lsum[j] += __shfl_xor_sync(0xffffffffu, lsum[j], 2);
    }

    // epilogue: O = (Vsum + D@V)/l, tf32-rounded, wperm layout (for proj)
    const float* vsb = g_vs + bh * DH;
    float inv0 = 1.f / lsum[0];
    float inv1 = 1.f / lsum[1];
    float* ob = g_o + (size_t)(b * TT + t0 + wrow + r8) * CC + h * DH;
#pragma unroll
    for (int dt = 0; dt < 8; dt++) {
        int c0 = dt * 8 + 2 * q4;
        float2 vsv = *(const float2*)(vsb + c0);
        int p0 = wperm(c0), p1 = wperm(c0 + 1);
        ob[p0] = __uint_as_float(f2tf((o[dt].x + vsv.x) * inv0));
        ob[p1] = __uint_as_float(f2tf((o[dt].y + vsv.y) * inv0));
        ob[8 * CC + p0] = __uint_as_float(f2tf((o[dt].z + vsv.x) * inv1));
        ob[8 * CC + p1] = __uint_as_float(f2tf((o[dt].w + vsv.y) * inv1));
    }
}

// ---------------------------------------------------------------------------
// Kernel 3: output projection, tf32 mma.sync, cp.async double-buffered.
// (Proven R10/R12 config: tile 128x128, k-chunk 32, QP 40, uint2 frag loads.)
// ---------------------------------------------------------------------------
#define QP 40
#define TILE_W (128 * QP)

__global__ void __launch_bounds__(256, 2)
proj_kernel(const float* __restrict__ bp, float* __restrict__ y)
{
    extern __shared__ __align__(1024) uint32_t smu[];
    const uint32_t smb = smem_u32(smu);

    const int tid  = threadIdx.x;
    const int lane = tid & 31;
    const int wid  = tid >> 5;
    const int q4   = lane & 3;
    const int r8   = lane >> 2;
    const int wm   = wid >> 1;
    const int wn   = wid & 1;

    const int e0 = blockIdx.x * 128;
    const int n0 = blockIdx.y * 128;

    const int frow = tid >> 3;
    const int fch  = (tid & 7) << 2;

    float4 c[2][8];
#pragma unroll
    for (int i = 0; i < 2; i++)
#pragma unroll
        for (int j = 0; j < 8; j++) c[i][j] = make_float4(0.f, 0.f, 0.f, 0.f);

#pragma unroll
    for (int i = 0; i < 4; i++) {
        int r = frow + i * 32;
        cp_async16(smb + (0 * 2 * TILE_W + r * QP + fch) * 4,
                   g_o + (size_t)(n0 + r) * CC + 0 + fch);
        cp_async16(smb + (0 * 2 * TILE_W + TILE_W + r * QP + fch) * 4,
                   g_wp + (size_t)(e0 + r) * CC + 0 + fch);
    }
    cp_commit();

    for (int it = 0; it < CC / 32; it++) {
        const int buf = it & 1;
        if (it + 1 < CC / 32) {
            int kt = (it + 1) * 32;
            int ob = buf ^ 1;
#pragma unroll
            for (int i = 0; i < 4; i++) {
                int r = frow + i * 32;
                cp_async16(smb + (ob * 2 * TILE_W + r * QP + fch) * 4,
                           g_o + (size_t)(n0 + r) * CC + kt + fch);
                cp_async16(smb + (ob * 2 * TILE_W + TILE_W + r * QP + fch) * 4,
                           g_wp + (size_t)(e0 + r) * CC + kt + fch);
            }
            cp_commit();
            asm volatile("cp.async.wait_group 1;\n" ::: "memory");
        } else {
            asm volatile("cp.async.wait_group 0;\n" ::: "memory");
        }
        __syncthreads();

        const uint32_t* ot = smu + buf * 2 * TILE_W;
        const uint32_t* wt = ot + TILE_W;

#pragma unroll
        for (int kk8 = 0; kk8 < 4; kk8++) {
            int off = kk8 * 8 + 2 * q4;
            uint2 a00 = *(const uint2*)(ot + (wm * 32 + r8)          * QP + off);
            uint2 a01 = *(const uint2*)(ot + (wm * 32 + r8 + 8)      * QP + off);
            uint2 a10 = *(const uint2*)(ot + (wm * 32 + 16 + r8)     * QP + off);
            uint2 a11 = *(const uint2*)(ot + (wm * 32 + 16 + r8 + 8) * QP + off);
#pragma unroll
            for (int ntl = 0; ntl < 8; ntl++) {
                uint2 bb = *(const uint2*)(wt + (wn * 64 + ntl * 8 + r8) * QP + off);
                mma_tf32(c[0][ntl], a00.x, a01.x, a00.y, a01.y, bb.x, bb.y);
                mma_tf32(c[1][ntl], a10.x, a11.x, a10.y, a11.y, bb.x, bb.y);
            }
        }
        __syncthreads();
    }

#pragma unroll
    for (int mt = 0; mt < 2; mt++) {
        int rrow = n0 + wm * 32 + mt * 16 + r8;
#pragma unroll
        for (int ntl = 0; ntl < 8; ntl++) {
            int col = e0 + wn * 64 + ntl * 8 + 2 * q4;
            float2 bb = *(const float2*)(bp + col);
            *(float2*)(y + (size_t)rrow * CC + col) =
                make_float2(c[mt][ntl].x + bb.x, c[mt][ntl].y + bb.y);
            *(float2*)(y + (size_t)(rrow + 8) * CC + col) =
                make_float2(c[mt][ntl].z + bb.x, c[mt][ntl].w + bb.y);
        }
    }
}

// ---------------------------------------------------------------------------
extern "C" void kernel_launch(void* const* d_in, const int* in_sizes, int n_in,
                              void* d_out, int out_size)
{
    (void)in_sizes; (void)n_in; (void)out_size;
    const float* x  = (const float*)d_in[0];
    const float* Wq = (const float*)d_in[1];
    const float* bq = (const float*)d_in[2];
    const float* Wk = (const float*)d_in[3];
    const float* bk = (const float*)d_in[4];
    const float* Wv = (const float*)d_in[5];
    const float* bv = (const float*)d_in[6];
    const float* Wp = (const float*)d_in[7];
    const float* bp = (const float*)d_in[8];
    float* y = (float*)d_out;

    const int smem1 = (128 * PITCH + 3 * 64 * PITCH) * 4;  // 92160
    const int smem2 = (4 * KVW) * 4;                       // 49152
    const int smem3 = (4 * TILE_W) * 4;                    // 81920

    cudaFuncSetAttribute(qkv_kernel,  cudaFuncAttributeMaxDynamicSharedMemorySize, smem1);
    cudaFuncSetAttribute(attn_kernel, cudaFuncAttributeMaxDynamicSharedMemorySize, smem2);
    cudaFuncSetAttribute(proj_kernel, cudaFuncAttributeMaxDynamicSharedMemorySize, smem3);

    wp_perm_kernel<<<CC * CC / 1024, 256>>>(Wp);
    qkv_kernel<<<dim3(TT / 128, HH, BB), 256, smem1>>>(x, Wq, bq, Wk, bk, Wv, bv);
    vsum_kernel<<<BB * HH, 256>>>();
    attn_kernel<<<dim3(TT / 128, HH, BB), 256, smem2>>>();
    proj_kernel<<<dim3(CC / 128, (BB * TT) / 128), 256, smem3>>>(bp, y);
}

// round 16
// speedup vs baseline: 1.5920x; 1.5920x over previous
#include <cuda_runtime.h>
#include <cuda_bf16.h>
#include <math.h>
#include <stdint.h>

#define BB 4
#define TT 2048
#define CC 1024
#define HH 16
#define DH 64

// Scratch (device globals: allocation-free)
__device__ __nv_bfloat16 g_qb[BB*HH*TT*DH];        // [b,h,t,d] bf16, scaled by log2e/32
__device__ __nv_bfloat16 g_kb[BB*HH*TT*DH];        // [b,h,t,d] bf16, word-permuted
__device__ __nv_bfloat16 g_vb[BB*HH*TT*DH];        // [b,h,d,t] bf16 (V^T), word-permuted
__device__ float g_vs[BB*HH*DH];                   // per-(b,h,d) sum of V over t
__device__ float g_o[BB*TT*CC];                    // [b,t,c] tf32-rounded, word-permuted
__device__ float g_wp[CC*CC];                      // Wp tf32-rounded, word-permuted

// ---------------------------------------------------------------------------
// helpers
// ---------------------------------------------------------------------------
__device__ __forceinline__ uint32_t f2tf(float f) {
    uint32_t u;
    asm("cvt.rna.tf32.f32 %0, %1;" : "=r"(u) : "f"(f));
    return u;
}

__device__ __forceinline__ float ex2f(float x) {
    float r;
    asm("ex2.approx.f32 %0, %1;" : "=f"(r) : "f"(x));
    return r;
}

__device__ __forceinline__ uint32_t pk_bf16(float lo, float hi) {
    __nv_bfloat162 t = __float22bfloat162_rn(make_float2(lo, hi));
    return *(uint32_t*)&t;
}

__device__ __forceinline__ void mma_tf32(float4& d,
                                         uint32_t a0, uint32_t a1, uint32_t a2, uint32_t a3,
                                         uint32_t b0, uint32_t b1) {
    asm volatile(
        "mma.sync.aligned.m16n8k8.row.col.f32.tf32.tf32.f32 "
        "{%0,%1,%2,%3}, {%4,%5,%6,%7}, {%8,%9}, {%0,%1,%2,%3};\n"
        : "+f"(d.x), "+f"(d.y), "+f"(d.z), "+f"(d.w)
        : "r"(a0), "r"(a1), "r"(a2), "r"(a3), "r"(b0), "r"(b1));
}

__device__ __forceinline__ void mma_bf16(float4& d,
                                         uint32_t a0, uint32_t a1, uint32_t a2, uint32_t a3,
                                         uint32_t b0, uint32_t b1) {
    asm volatile(
        "mma.sync.aligned.m16n8k16.row.col.f32.bf16.bf16.f32 "
        "{%0,%1,%2,%3}, {%4,%5,%6,%7}, {%8,%9}, {%0,%1,%2,%3};\n"
        : "+f"(d.x), "+f"(d.y), "+f"(d.z), "+f"(d.w)
        : "r"(a0), "r"(a1), "r"(a2), "r"(a3), "r"(b0), "r"(b1));
}

__device__ __forceinline__ void perm_st4(uint32_t* rowp, int c4, float4 v) {
    int g = (c4 & ~7) + ((c4 & 4) >> 2);
    rowp[g + 0] = f2tf(v.x);
    rowp[g + 2] = f2tf(v.y);
    rowp[g + 4] = f2tf(v.z);
    rowp[g + 6] = f2tf(v.w);
}

#define PITCH 72   // qkv interleaved tf32 smem pitch

__device__ __forceinline__ uint32_t smem_u32(const void* p) {
    uint32_t a;
    asm("{ .reg .u64 t; cvta.to.shared.u64 t, %1; cvt.u32.u64 %0, t; }"
        : "=r"(a) : "l"(p));
    return a;
}

__device__ __forceinline__ void cp_async16(uint32_t dst, const void* src) {
    asm volatile("cp.async.cg.shared.global [%0], [%1], 16;\n"
                 :: "r"(dst), "l"(src) : "memory");
}
__device__ __forceinline__ void cp_commit() {
    asm volatile("cp.async.commit_group;\n" ::: "memory");
}
__device__ __forceinline__ void cp_wait0() {
    asm volatile("cp.async.wait_group 0;\n" ::: "memory");
}

// word-permutation within 8-word groups: logical word w -> slot
// ((w&3)<<1)|((w>>2)&1); mma pair-words (q4, q4+4) become adjacent -> LDS.64.
__device__ __forceinline__ int wperm(int w) {
    return (w & ~7) | ((w & 3) << 1) | ((w >> 2) & 1);
}
// same permutation on bf16 element index within 16-elem groups
__device__ __forceinline__ int tperm(int t) {
    int w = (t >> 1) & 7;
    return (t & ~15) | ((((w & 3) << 1) | ((w >> 2) & 1)) << 1) | (t & 1);
}

// ---------------------------------------------------------------------------
// Kernel 0: Wp -> g_wp (tf32 rna-rounded, word-permuted).
// ---------------------------------------------------------------------------
__global__ void __launch_bounds__(256, 4) wp_perm_kernel(const float* __restrict__ Wp)
{
    int idx = blockIdx.x * 256 + threadIdx.x;
    int row = idx >> 8;
    int c4  = (idx & 255) << 2;
    float4 v = *(const float4*)(Wp + (size_t)row * CC + c4);
    float* dst = g_wp + (size_t)row * CC + (c4 & ~7) + ((c4 & 4) >> 2);
    dst[0] = __uint_as_float(f2tf(v.x));
    dst[2] = __uint_as_float(f2tf(v.y));
    dst[4] = __uint_as_float(f2tf(v.z));
    dst[6] = __uint_as_float(f2tf(v.w));
}

// ---------------------------------------------------------------------------
// Kernel 1: per-head QKV projection, tf32 mma.sync (rna). (R12 exact)
// ---------------------------------------------------------------------------
__global__ void __launch_bounds__(256, 2)
qkv_kernel(const float* __restrict__ x,
           const float* __restrict__ Wq, const float* __restrict__ bq,
           const float* __restrict__ Wk, const float* __restrict__ bk,
           const float* __restrict__ Wv, const float* __restrict__ bv)
{
    extern __shared__ uint32_t smu[];
    uint32_t* xs = smu;
    uint32_t* ws = smu + 128 * PITCH;

    const int tid  = threadIdx.x;
    const int lane = tid & 31;
    const int wid  = tid >> 5;
    const int q4   = lane & 3;
    const int r8   = lane >> 2;
    const int wm   = wid >> 1;
    const int wn   = wid & 1;

    const int t0 = blockIdx.x * 128;
    const int h  = blockIdx.y;
    const int b  = blockIdx.z;
    const size_t bh = (size_t)(b * HH + h);

    const int lrow = tid >> 4;
    const int lc4  = (tid & 15) << 2;

    const float* xb = x + (size_t)(b * TT + t0) * CC + h * DH;
#pragma unroll
    for (int i = 0; i < 8; i++) {
        int r = lrow + i * 16;
        float4 v = *(const float4*)(xb + (size_t)r * CC + lc4);
        perm_st4(xs + r * PITCH, lc4, v);
    }
    {
        const float* Ws[3] = {Wq, Wk, Wv};
#pragma unroll
        for (int m = 0; m < 3; m++) {
            uint32_t* wsm = ws + m * 64 * PITCH;
#pragma unroll
            for (int i = 0; i < 4; i++) {
                int r = lrow + i * 16;
                float4 v = *(const float4*)(Ws[m] + r * 64 + lc4);
                perm_st4(wsm + r * PITCH, lc4, v);
            }
        }
    }
    __syncthreads();

    const float* bias[3] = {bq, bk, bv};
#pragma unroll
    for (int m = 0; m < 3; m++) {
        const uint32_t* wsm = ws + m * 64 * PITCH;
        float4 c[2][4];
#pragma unroll
        for (int i = 0; i < 2; i++)
#pragma unroll
            for (int j = 0; j < 4; j++) c[i][j] = make_float4(0.f, 0.f, 0.f, 0.f);

#pragma unroll
        for (int kk8 = 0; kk8 < 8; kk8++) {
            int off = kk8 * 8 + 2 * q4;
            uint2 a00 = *(const uint2*)(xs + (wm * 32 + r8)          * PITCH + off);
            uint2 a01 = *(const uint2*)(xs + (wm * 32 + r8 + 8)      * PITCH + off);
            uint2 a10 = *(const uint2*)(xs + (wm * 32 + 16 + r8)     * PITCH + off);
            uint2 a11 = *(const uint2*)(xs + (wm * 32 + 16 + r8 + 8) * PITCH + off);
#pragma unroll
            for (int ntl = 0; ntl < 4; ntl++) {
                uint2 bb = *(const uint2*)(wsm + (wn * 32 + ntl * 8 + r8) * PITCH + off);
                mma_tf32(c[0][ntl], a00.x, a01.x, a00.y, a01.y, bb.x, bb.y);
                mma_tf32(c[1][ntl], a10.x, a11.x, a10.y, a11.y, bb.x, bb.y);
            }
        }

        if (m == 0) {
            uint32_t* qw = (uint32_t*)g_qb + (bh * TT + t0) * (DH / 2);
            const float s = 0.03125f * 1.44269504088896f;
#pragma unroll
            for (int mt = 0; mt < 2; mt++) {
                int row = wm * 32 + mt * 16 + r8;
#pragma unroll
                for (int ntl = 0; ntl < 4; ntl++) {
                    int e = wn * 32 + ntl * 8 + 2 * q4;
                    float2 bb = *(const float2*)(bias[0] + e);
                    qw[(size_t)row * 32 + (e >> 1)] =
                        pk_bf16((c[mt][ntl].x + bb.x) * s, (c[mt][ntl].y + bb.y) * s);
                    qw[(size_t)(row + 8) * 32 + (e >> 1)] =
                        pk_bf16((c[mt][ntl].z + bb.x) * s, (c[mt][ntl].w + bb.y) * s);
                }
            }
        } else if (m == 1) {
            uint32_t* kbw = (uint32_t*)g_kb + (bh * TT + t0) * (DH / 2);
#pragma unroll
            for (int mt = 0; mt < 2; mt++) {
                int row = wm * 32 + mt * 16 + r8;
#pragma unroll
                for (int ntl = 0; ntl < 4; ntl++) {
                    int e = wn * 32 + ntl * 8 + 2 * q4;
                    float2 bb = *(const float2*)(bias[1] + e);
                    int wp = wperm(e >> 1);
                    kbw[(size_t)row * 32 + wp] =
                        pk_bf16(c[mt][ntl].x + bb.x, c[mt][ntl].y + bb.y);
                    kbw[(size_t)(row + 8) * 32 + wp] =
                        pk_bf16(c[mt][ntl].z + bb.x, c[mt][ntl].w + bb.y);
                }
            }
        } else {
            __nv_bfloat16* vbb = g_vb + bh * DH * TT;
#pragma unroll
            for (int mt = 0; mt < 2; mt++) {
                int t = t0 + wm * 32 + mt * 16 + r8;
                int tp0 = tperm(t), tp8 = tperm(t + 8);
#pragma unroll
                for (int ntl = 0; ntl < 4; ntl++) {
                    int e = wn * 32 + ntl * 8 + 2 * q4;
                    float2 bb = *(const float2*)(bias[2] + e);
                    vbb[(size_t)e       * TT + tp0] = __float2bfloat16_rn(c[mt][ntl].x + bb.x);
                    vbb[(size_t)(e + 1) * TT + tp0] = __float2bfloat16_rn(c[mt][ntl].y + bb.y);
                    vbb[(size_t)e       * TT + tp8] = __float2bfloat16_rn(c[mt][ntl].z + bb.x);
                    vbb[(size_t)(e + 1) * TT + tp8] = __float2bfloat16_rn(c[mt][ntl].w + bb.y);
                }
            }
        }
    }
}

// ---------------------------------------------------------------------------
// Kernel 1b: Vsum[b,h,d] = sum_t V[b,h,d,t] (bf16 rows, fp32 accumulation)
// ---------------------------------------------------------------------------
__global__ void __launch_bounds__(256, 4) vsum_kernel()
{
    const int bh   = blockIdx.x;
    const int lane = threadIdx.x & 31;
    const int w    = threadIdx.x >> 5;
    const __nv_bfloat16* vb = g_vb + (size_t)bh * DH * TT;

#pragma unroll
    for (int pass = 0; pass < 8; pass++) {
        int d = pass * 8 + w;
        const uint4* row = (const uint4*)(vb + (size_t)d * TT);
        float s = 0.f;
#pragma unroll
        for (int i = 0; i < 8; i++) {
            uint4 u = row[lane + i * 32];
            float2 f0 = __bfloat1622float2(*(__nv_bfloat162*)&u.x);
            float2 f1 = __bfloat1622float2(*(__nv_bfloat162*)&u.y);
            float2 f2 = __bfloat1622float2(*(__nv_bfloat162*)&u.z);
            float2 f3 = __bfloat1622float2(*(__nv_bfloat162*)&u.w);
            s += (f0.x + f0.y) + (f1.x + f1.y) + (f2.x + f2.y) + (f3.x + f3.y);
        }
        s += __shfl_xor_sync(0xffffffffu, s, 16);
        s += __shfl_xor_sync(0xffffffffu, s, 8);
        s += __shfl_xor_sync(0xffffffffu, s, 4);
        s += __shfl_xor_sync(0xffffffffu, s, 2);
        s += __shfl_xor_sync(0xffffffffu, s, 1);
        if (lane == 0) g_vs[bh * DH + d] = s;
    }
}

// ---------------------------------------------------------------------------
// Kernel 2: flash attention, bf16 m16n8k16, BM=128, 256 threads, 2 CTAs/SM.
// Software-pipelined stages: per K-tile, S chains for key-blocks j+2 are
// issued between exp(j) and PV(j), interleaving MUFU with tensor within one
// warp. Identical instruction set to R12 winner (LDS.64, pure ex2, Sum p).
// ---------------------------------------------------------------------------
#define BP 40
#define KVW (64 * BP)

__global__ void __launch_bounds__(256, 2) attn_kernel()
{
    extern __shared__ __align__(1024) uint32_t smu[];

    const int tid  = threadIdx.x;
    const int lane = tid & 31;
    const int wid  = tid >> 5;        // 0..7
    const int q4   = lane & 3;
    const int r8   = lane >> 2;
    const int wrow = wid * 16;

    const int t0 = blockIdx.x * 128;
    const int h  = blockIdx.y;
    const int b  = blockIdx.z;
    const size_t bh = (size_t)(b * HH + h);

    const __nv_bfloat16* kbb = g_kb + bh * TT * DH;
    const __nv_bfloat16* vbb = g_vb + bh * DH * TT;

    const uint32_t smb = smem_u32(smu);

    const int frow[2] = { (tid + 0) >> 3, (tid + 256) >> 3 };
    const int fch     = tid & 7;

    // Q fragments (bf16 pre-scaled by log2e/32, natural words)
    uint32_t qf[4][4];
    {
        const uint32_t* q0 = (const uint32_t*)g_qb +
                             (bh * TT + t0 + wrow + r8) * (DH / 2);
        const uint32_t* q1 = q0 + 8 * (DH / 2);
#pragma unroll
        for (int kk = 0; kk < 4; kk++) {
            qf[kk][0] = q0[kk * 8 + q4];
            qf[kk][1] = q1[kk * 8 + q4];
            qf[kk][2] = q0[kk * 8 + q4 + 4];
            qf[kk][3] = q1[kk * 8 + q4 + 4];
        }
    }

    float4 o[8];
#pragma unroll
    for (int j = 0; j < 8; j++) o[j] = make_float4(0.f, 0.f, 0.f, 0.f);
    float lsum[2] = {0.f, 0.f};

#pragma unroll
    for (int i = 0; i < 2; i++) {
        int r = frow[i];
        cp_async16(smb + (0 * KVW + r * BP + fch * 4) * 4,
                   kbb + (size_t)r * DH + fch * 8);
        cp_async16(smb + (1 * KVW + r * BP + fch * 4) * 4,
                   vbb + (size_t)r * TT + 0 + fch * 8);
    }
    cp_commit();

    for (int it = 0; it < TT / 64; it++) {
        cp_wait0();
        __syncthreads();

        const int buf = it & 1;
        const uint32_t* ks = smu + (2 * buf + 0) * KVW;
        const uint32_t* vs = smu + (2 * buf + 1) * KVW;

        if (it + 1 < TT / 64) {
            int nt = (it + 1) * 64;
            int ob = buf ^ 1;
#pragma unroll
            for (int i = 0; i < 2; i++) {
                int r = frow[i];
                cp_async16(smb + ((2 * ob + 0) * KVW + r * BP + fch * 4) * 4,
                           kbb + (size_t)(nt + r) * DH + fch * 8);
                cp_async16(smb + ((2 * ob + 1) * KVW + r * BP + fch * 4) * 4,
                           vbb + (size_t)r * TT + nt + fch * 8);
            }
            cp_commit();
        }

        float4 c[8];
#pragma unroll
        for (int j = 0; j < 8; j++) c[j] = make_float4(0.f, 0.f, 0.f, 0.f);

        // ---- prologue: S chains for key-blocks 0 and 1 (ntl 0..3) ----
#pragma unroll
        for (int kk = 0; kk < 4; kk++) {
#pragma unroll
            for (int ntl = 0; ntl < 4; ntl++) {
                uint2 bb = *(const uint2*)(ks + (ntl * 8 + r8) * BP + kk * 8 + 2 * q4);
                mma_bf16(c[ntl], qf[kk][0], qf[kk][1], qf[kk][2], qf[kk][3],
                         bb.x, bb.y);
            }
        }

        // ---- pipelined stages: exp(j) | PV(j) | S chains for block j+2 ----
#pragma unroll
        for (int j = 0; j < 4; j++) {
            // exp + pack for key-block j (c[2j], c[2j+1])
            float4 cA = c[2 * j];
            float4 cB = c[2 * j + 1];
            float pax = ex2f(cA.x), pay = ex2f(cA.y);
            float paz = ex2f(cA.z), paw = ex2f(cA.w);
            float pbx = ex2f(cB.x), pby = ex2f(cB.y);
            float pbz = ex2f(cB.z), pbw = ex2f(cB.w);
            lsum[0] += (pax + pay) + (pbx + pby);
            lsum[1] += (paz + paw) + (pbz + pbw);
            uint32_t a0 = pk_bf16(pax - 1.f, pay - 1.f);
            uint32_t a1 = pk_bf16(paz - 1.f, paw - 1.f);
            uint32_t a2 = pk_bf16(pbx - 1.f, pby - 1.f);
            uint32_t a3 = pk_bf16(pbz - 1.f, pbw - 1.f);

            // PV MMAs for key-block j (tensor) — interleaves with exps above
#pragma unroll
            for (int dt = 0; dt < 8; dt++) {
                uint2 bb = *(const uint2*)(vs + (dt * 8 + r8) * BP + j * 8 + 2 * q4);
                mma_bf16(o[dt], a0, a1, a2, a3, bb.x, bb.y);
            }

            // S chains for key-block j+2 (ntl 2j+4, 2j+5)
            if (j < 2) {
#pragma unroll
                for (int kk = 0; kk < 4; kk++) {
#pragma unroll
                    for (int nn = 0; nn < 2; nn++) {
                        int ntl = 2 * j + 4 + nn;
                        uint2 bb = *(const uint2*)(ks + (ntl * 8 + r8) * BP + kk * 8 + 2 * q4);
                        mma_bf16(c[ntl], qf[kk][0], qf[kk][1], qf[kk][2], qf[kk][3],
                                 bb.x, bb.y);
                    }
                }
            }
        }
    }

    // final l reduction across the quad
#pragma unroll
    for (int j = 0; j < 2; j++) {
        lsum[j] += __shfl_xor_sync(0xffffffffu, lsum[j], 1);
        lsum[j] += __shfl_xor_sync(0xffffffffu, lsum[j], 2);
    }

    // epilogue: O = (Vsum + D@V)/l, tf32-rounded + word-permuted
    const float* vsb = g_vs + bh * DH;
    float inv0 = 1.f / lsum[0];
    float inv1 = 1.f / lsum[1];
    float* ob = g_o + (size_t)(b * TT + t0 + wrow + r8) * CC + h * DH;
#pragma unroll
    for (int dt = 0; dt < 8; dt++) {
        int c0 = dt * 8 + 2 * q4;
        float2 vsv = *(const float2*)(vsb + c0);
        int p0 = wperm(c0), p1 = wperm(c0 + 1);
        ob[p0] = __uint_as_float(f2tf((o[dt].x + vsv.x) * inv0));
        ob[p1] = __uint_as_float(f2tf((o[dt].y + vsv.y) * inv0));
        ob[8 * CC + p0] = __uint_as_float(f2tf((o[dt].z + vsv.x) * inv1));
        ob[8 * CC + p1] = __uint_as_float(f2tf((o[dt].w + vsv.y) * inv1));
    }
}

// ---------------------------------------------------------------------------
// Kernel 3: output projection, tf32 mma.sync, cp.async double-buffered.
// (Proven R10/R12 config: tile 128x128, k-chunk 32, QP 40, uint2 frag loads.)
// ---------------------------------------------------------------------------
#define QP 40
#define TILE_W (128 * QP)

__global__ void __launch_bounds__(256, 2)
proj_kernel(const float* __restrict__ bp, float* __restrict__ y)
{
    extern __shared__ __align__(1024) uint32_t smu[];
    const uint32_t smb = smem_u32(smu);

    const int tid  = threadIdx.x;
    const int lane = tid & 31;
    const int wid  = tid >> 5;
    const int q4   = lane & 3;
    const int r8   = lane >> 2;
    const int wm   = wid >> 1;
    const int wn   = wid & 1;

    const int e0 = blockIdx.x * 128;
    const int n0 = blockIdx.y * 128;

    const int frow = tid >> 3;
    const int fch  = (tid & 7) << 2;

    float4 c[2][8];
#pragma unroll
    for (int i = 0; i < 2; i++)
#pragma unroll
        for (int j = 0; j < 8; j++) c[i][j] = make_float4(0.f, 0.f, 0.f, 0.f);

#pragma unroll
    for (int i = 0; i < 4; i++) {
        int r = frow + i * 32;
        cp_async16(smb + (0 * 2 * TILE_W + r * QP + fch) * 4,
                   g_o + (size_t)(n0 + r) * CC + 0 + fch);
        cp_async16(smb + (0 * 2 * TILE_W + TILE_W + r * QP + fch) * 4,
                   g_wp + (size_t)(e0 + r) * CC + 0 + fch);
    }
    cp_commit();

    for (int it = 0; it < CC / 32; it++) {
        const int buf = it & 1;
        if (it + 1 < CC / 32) {
            int kt = (it + 1) * 32;
            int ob = buf ^ 1;
#pragma unroll
            for (int i = 0; i < 4; i++) {
                int r = frow + i * 32;
                cp_async16(smb + (ob * 2 * TILE_W + r * QP + fch) * 4,
                           g_o + (size_t)(n0 + r) * CC + kt + fch);
                cp_async16(smb + (ob * 2 * TILE_W + TILE_W + r * QP + fch) * 4,
                           g_wp + (size_t)(e0 + r) * CC + kt + fch);
            }
            cp_commit();
            asm volatile("cp.async.wait_group 1;\n" ::: "memory");
        } else {
            asm volatile("cp.async.wait_group 0;\n" ::: "memory");
        }
        __syncthreads();

        const uint32_t* ot = smu + buf * 2 * TILE_W;
        const uint32_t* wt = ot + TILE_W;

#pragma unroll
        for (int kk8 = 0; kk8 < 4; kk8++) {
            int off = kk8 * 8 + 2 * q4;
            uint2 a00 = *(const uint2*)(ot + (wm * 32 + r8)          * QP + off);
            uint2 a01 = *(const uint2*)(ot + (wm * 32 + r8 + 8)      * QP + off);
            uint2 a10 = *(const uint2*)(ot + (wm * 32 + 16 + r8)     * QP + off);
            uint2 a11 = *(const uint2*)(ot + (wm * 32 + 16 + r8 + 8) * QP + off);
#pragma unroll
            for (int ntl = 0; ntl < 8; ntl++) {
                uint2 bb = *(const uint2*)(wt + (wn * 64 + ntl * 8 + r8) * QP + off);
                mma_tf32(c[0][ntl], a00.x, a01.x, a00.y, a01.y, bb.x, bb.y);
                mma_tf32(c[1][ntl], a10.x, a11.x, a10.y, a11.y, bb.x, bb.y);
            }
        }
        __syncthreads();
    }

#pragma unroll
    for (int mt = 0; mt < 2; mt++) {
        int rrow = n0 + wm * 32 + mt * 16 + r8;
#pragma unroll
        for (int ntl = 0; ntl < 8; ntl++) {
            int col = e0 + wn * 64 + ntl * 8 + 2 * q4;
            float2 bb = *(const float2*)(bp + col);
            *(float2*)(y + (size_t)rrow * CC + col) =
                make_float2(c[mt][ntl].x + bb.x, c[mt][ntl].y + bb.y);
            *(float2*)(y + (size_t)(rrow + 8) * CC + col) =
                make_float2(c[mt][ntl].z + bb.x, c[mt][ntl].w + bb.y);
        }
    }
}

// ---------------------------------------------------------------------------
extern "C" void kernel_launch(void* const* d_in, const int* in_sizes, int n_in,
                              void* d_out, int out_size)
{
    (void)in_sizes; (void)n_in; (void)out_size;
    const float* x  = (const float*)d_in[0];
    const float* Wq = (const float*)d_in[1];
    const float* bq = (const float*)d_in[2];
    const float* Wk = (const float*)d_in[3];
    const float* bk = (const float*)d_in[4];
    const float* Wv = (const float*)d_in[5];
    const float* bv = (const float*)d_in[6];
    const float* Wp = (const float*)d_in[7];
    const float* bp = (const float*)d_in[8];
    float* y = (float*)d_out;

    const int smem1 = (128 * PITCH + 3 * 64 * PITCH) * 4;  // 92160
    const int smem2 = (4 * KVW) * 4;                       // 40960
    const int smem3 = (4 * TILE_W) * 4;                    // 81920

    cudaFuncSetAttribute(qkv_kernel,  cudaFuncAttributeMaxDynamicSharedMemorySize, smem1);
    cudaFuncSetAttribute(attn_kernel, cudaFuncAttributeMaxDynamicSharedMemorySize, smem2);
    cudaFuncSetAttribute(proj_kernel, cudaFuncAttributeMaxDynamicSharedMemorySize, smem3);

    wp_perm_kernel<<<CC * CC / 1024, 256>>>(Wp);
    qkv_kernel<<<dim3(TT / 128, HH, BB), 256, smem1>>>(x, Wq, bq, Wk, bk, Wv, bv);
    vsum_kernel<<<BB * HH, 256>>>();
    attn_kernel<<<dim3(TT / 128, HH, BB), 256, smem2>>>();
    proj_kernel<<<dim3(CC / 128, (BB * TT) / 128), 256, smem3>>>(bp, y);
}